// round 5
// baseline (speedup 1.0000x reference)
#include <cuda_runtime.h>
#include <math.h>

#define B_    2
#define L_    4096
#define K_    32
#define HALF_ 128
#define NPAIR 28
#define EPSF  1e-6f
#define TWOPI 6.28318530717958647692f
#define BL_   (B_*L_)

typedef unsigned long long ull;

__device__ float g_wsym[NPAIR*HALF_];   // 2pi*(W[mn]+W[nm])
__device__ float g_wv[3*HALF_];         // 2pi*W_vec
__device__ float g_bias[HALF_];         // 2pi*sqrt(EPS)*sum_diag W

__constant__ int c_pm[NPAIR] = {0,0,0,0,0,0,0,1,1,1,1,1,1,2,2,2,2,2,3,3,3,3,4,4,4,5,5,6};
__constant__ int c_pn[NPAIR] = {1,2,3,4,5,6,7,2,3,4,5,6,7,3,4,5,6,7,4,5,6,7,5,6,7,6,7,7};

static __device__ __forceinline__ ull pack2(float lo, float hi){
    ull r; asm("mov.b64 %0, {%1,%2};" : "=l"(r) : "f"(lo), "f"(hi)); return r;
}
static __device__ __forceinline__ void unpack2(ull v, float& lo, float& hi){
    asm("mov.b64 {%0,%1}, %2;" : "=f"(lo), "=f"(hi) : "l"(v));
}
static __device__ __forceinline__ ull fma2(ull a, ull b, ull c){
    ull d; asm("fma.rn.f32x2 %0, %1, %2, %3;" : "=l"(d) : "l"(a), "l"(b), "l"(c)); return d;
}
static __device__ __forceinline__ ull mul2(ull a, ull b){
    ull d; asm("mul.rn.f32x2 %0, %1, %2;" : "=l"(d) : "l"(a), "l"(b)); return d;
}
static __device__ __forceinline__ ull dup2(float x){ return pack2(x, x); }

// ---------------------------------------------------------------------------
// W preparation: fold 2pi, symmetrize W_dist over pairs, diagonal bias
// ---------------------------------------------------------------------------
__global__ void wprep_kernel(const float* __restrict__ Wvec, const float* __restrict__ Wdist){
    int e = threadIdx.x;  // 0..127
    #pragma unroll
    for (int d = 0; d < 3; d++) g_wv[d*HALF_ + e] = TWOPI * Wvec[d*HALF_ + e];
    float b = 0.f;
    #pragma unroll
    for (int m = 0; m < 8; m++) b += Wdist[(m*8+m)*HALF_ + e];
    g_bias[e] = TWOPI * sqrtf(EPSF) * b;
    for (int p = 0; p < NPAIR; p++){
        int m = c_pm[p], n = c_pn[p];
        g_wsym[p*HALF_ + e] = TWOPI * (Wdist[(m*8+n)*HALF_ + e] + Wdist[(n*8+m)*HALF_ + e]);
    }
}

// ---------------------------------------------------------------------------
// Main kernel: one block per residue, 256 thr = 8 warps.
// Warp (cg, eg): cg = col half (64 cols, 2/lane), eg = 8-edge group.
// ---------------------------------------------------------------------------
__global__ __launch_bounds__(256, 3)
void edge_kernel(const float* __restrict__ X, const void* __restrict__ eidxv,
                 const void* __restrict__ Cv, float* __restrict__ out){
    __shared__ float s_wsym[NPAIR*HALF_];   // 14336 B
    __shared__ float s_wv[3*HALF_];         // 1536 B
    __shared__ float s_bias[HALF_];         // 512 B
    __shared__ float s_fr[12];
    __shared__ float s_xi[12];
    __shared__ float s_xj[K_*12];           // 1536 B
    __shared__ float s_mj[K_];
    __shared__ float s_d[K_*NPAIR];         // 3584 B: s_d[edge*28 + pair]
    __shared__ int   s_is64[2];

    int tid  = threadIdx.x;
    int res  = blockIdx.x;
    int bbase = res & ~(L_-1);

    // --- inline dtype detection: int64 buffers have zero odd 32-bit words ---
    if (tid < 64){
        const int4* p = (tid < 32) ? (const int4*)eidxv : (const int4*)Cv;
        int4 v = p[tid & 31];
        int o = v.y | v.w;
        o = __reduce_or_sync(0xffffffffu, o);
        if ((tid & 31) == 0) s_is64[tid >> 5] = (o == 0);
    }
    __syncthreads();
    int is64  = s_is64[0];
    int is64C = s_is64[1];

    // --- cooperative staging ---
    {
        const float4* src = (const float4*)g_wsym;
        float4* dst = (float4*)s_wsym;
        #pragma unroll
        for (int i = tid; i < NPAIR*HALF_/4; i += 256) dst[i] = src[i];
    }
    if (tid < 96)                  ((float4*)s_wv)[tid]      = ((const float4*)g_wv)[tid];
    if (tid >= 96 && tid < 128)    ((float4*)s_bias)[tid-96] = ((const float4*)g_bias)[tid-96];
    if (tid >= 96 && tid < 99)     ((float4*)s_xi)[tid-96]   = ((const float4*)X)[res*3 + (tid-96)];
    if (tid >= 128 && tid < 128 + K_*3){
        int t = tid - 128;
        int kk = t/3, part = t - kk*3;
        long long j = is64 ? ((const long long*)eidxv)[res*K_ + kk]
                           : (long long)((const int*)eidxv)[res*K_ + kk];
        ((float4*)&s_xj[kk*12])[part] = ((const float4*)X)[(bbase + (int)j)*3 + part];
    }
    if (tid >= 224){
        int kk = tid - 224;
        long long j = is64 ? ((const long long*)eidxv)[res*K_ + kk]
                           : (long long)((const int*)eidxv)[res*K_ + kk];
        int jg = bbase + (int)j;
        long long cval = is64C ? ((const long long*)Cv)[jg]
                               : (long long)((const int*)Cv)[jg];
        s_mj[kk] = (cval > 0) ? 1.f : 0.f;
    }
    if (tid == 99){
        // frames for own residue
        const float* x = X + (size_t)res * 12;
        float Nx=x[0], Ny=x[1], Nz=x[2];
        float Ax=x[3], Ay=x[4], Az=x[5];
        float Cx=x[6], Cy=x[7], Cz=x[8];
        long long cv = is64C ? ((const long long*)Cv)[res] : (long long)((const int*)Cv)[res];
        float mask = (cv > 0) ? 1.f : 0.f;

        float v1x=Nx-Ax, v1y=Ny-Ay, v1z=Nz-Az;
        float n1 = sqrtf(v1x*v1x + v1y*v1y + v1z*v1z) + EPSF;
        float e1x=v1x/n1, e1y=v1y/n1, e1z=v1z/n1;

        float u2x=Cx-Ax, u2y=Cy-Ay, u2z=Cz-Az;
        float n2 = sqrtf(u2x*u2x + u2y*u2y + u2z*u2z) + EPSF;
        u2x/=n2; u2y/=n2; u2z/=n2;

        float dt = u2x*e1x + u2y*e1y + u2z*e1z;
        float w2x = u2x - dt*e1x, w2y = u2y - dt*e1y, w2z = u2z - dt*e1z;
        float n3 = sqrtf(w2x*w2x + w2y*w2y + w2z*w2z) + EPSF;
        float e2x=w2x/n3, e2y=w2y/n3, e2z=w2z/n3;

        float e3x = e1y*e2z - e1z*e2y;
        float e3y = e1z*e2x - e1x*e2z;
        float e3z = e1x*e2y - e1y*e2x;

        s_fr[0]=mask*e1x; s_fr[1]=mask*e1y; s_fr[2]=mask*e1z;
        s_fr[3]=mask*e2x; s_fr[4]=mask*e2y; s_fr[5]=mask*e2z;
        s_fr[6]=mask*e3x; s_fr[7]=mask*e3y; s_fr[8]=mask*e3z;
        s_fr[9]=mask*Ax;  s_fr[10]=mask*Ay; s_fr[11]=mask*Az;
    }
    __syncthreads();

    int w = tid >> 5, lane = tid & 31;

    // --- distances: warp w computes pairs for edges w*4..w*4+3, lane = pair ---
    if (lane < NPAIR){
        int m = c_pm[lane], n = c_pn[lane];
        bool mI = (m < 4), nI = (n < 4);
        float mx=0.f,my=0.f,mz=0.f, nx=0.f,ny=0.f,nz=0.f;
        if (mI){ mx=s_xi[m*3]; my=s_xi[m*3+1]; mz=s_xi[m*3+2]; }
        if (nI){ nx=s_xi[n*3]; ny=s_xi[n*3+1]; nz=s_xi[n*3+2]; }
        #pragma unroll
        for (int e = 0; e < 4; e++){
            int k = w*4 + e;
            const float* xj = &s_xj[k*12];
            float ax = mI ? mx : xj[(m-4)*3+0];
            float ay = mI ? my : xj[(m-4)*3+1];
            float az = mI ? mz : xj[(m-4)*3+2];
            float bx = nI ? nx : xj[(n-4)*3+0];
            float by = nI ? ny : xj[(n-4)*3+1];
            float bz = nI ? nz : xj[(n-4)*3+2];
            float dx=ax-bx, dy=ay-by, dz=az-bz;
            float dd = fmaf(dx,dx, fmaf(dy,dy, fmaf(dz,dz, EPSF)));
            s_d[k*NPAIR + lane] = __fsqrt_rn(dd);
        }
    }
    __syncthreads();

    int cg = w >> 2;            // column half: 0 or 1
    int eg = w & 3;             // edge group: 8 edges
    int col = cg*64 + lane*2;   // 2 columns per lane

    // --- hd = bias + sum_p D_p * Wsym_p : 1 f32x2 accumulator x 8 edges ---
    ull hd[8];
    {
        float2 bq = *(const float2*)&s_bias[col];
        ull b2 = pack2(bq.x, bq.y);
        #pragma unroll
        for (int e = 0; e < 8; e++) hd[e] = b2;
    }
    #pragma unroll 1
    for (int pp = 0; pp < NPAIR; pp += 4){
        float2 q0 = *(const float2*)&s_wsym[(pp+0)*HALF_ + col];
        float2 q1 = *(const float2*)&s_wsym[(pp+1)*HALF_ + col];
        float2 q2 = *(const float2*)&s_wsym[(pp+2)*HALF_ + col];
        float2 q3 = *(const float2*)&s_wsym[(pp+3)*HALF_ + col];
        ull W0 = pack2(q0.x,q0.y), W1 = pack2(q1.x,q1.y);
        ull W2 = pack2(q2.x,q2.y), W3 = pack2(q3.x,q3.y);
        #pragma unroll
        for (int e = 0; e < 8; e++){
            float4 dq = *(const float4*)&s_d[(eg*8+e)*NPAIR + pp];  // broadcast
            hd[e] = fma2(dup2(dq.x), W0, hd[e]);
            hd[e] = fma2(dup2(dq.y), W1, hd[e]);
            hd[e] = fma2(dup2(dq.z), W2, hd[e]);
            hd[e] = fma2(dup2(dq.w), W3, hd[e]);
        }
    }

    // --- fused epilogue: hv, sincos, store ---
    float e1x=s_fr[0], e1y=s_fr[1], e1z=s_fr[2];
    float e2x=s_fr[3], e2y=s_fr[4], e2z=s_fr[5];
    float e3x=s_fr[6], e3y=s_fr[7], e3z=s_fr[8];
    float tix=s_fr[9], tiy=s_fr[10], tiz=s_fr[11];
    float2 wv0 = *(const float2*)&s_wv[0*HALF_ + col];
    float2 wv1 = *(const float2*)&s_wv[1*HALF_ + col];
    float2 wv2 = *(const float2*)&s_wv[2*HALF_ + col];
    ull v0 = pack2(wv0.x, wv0.y);
    ull v1 = pack2(wv1.x, wv1.y);
    ull v2 = pack2(wv2.x, wv2.y);

    #pragma unroll
    for (int e = 0; e < 8; e++){
        int k = eg*8 + e;
        float mj = s_mj[k];
        float dx = fmaf(mj, s_xj[k*12+3], -tix);
        float dy = fmaf(mj, s_xj[k*12+4], -tiy);
        float dz = fmaf(mj, s_xj[k*12+5], -tiz);
        float t0 = fmaf(e1z,dz, fmaf(e1y,dy, e1x*dx));
        float t1 = fmaf(e2z,dz, fmaf(e2y,dy, e2x*dx));
        float t2 = fmaf(e3z,dz, fmaf(e3y,dy, e3x*dx));
        ull hv = fma2(dup2(t2), v2, fma2(dup2(t1), v1, mul2(dup2(t0), v0)));

        float a0,a1,b0,b1;
        unpack2(hv, a0, a1);
        unpack2(hd[e], b0, b1);
        float sa0,ca0,sa1,ca1,sb0,cb0,sb1,cb1;
        __sincosf(a0,&sa0,&ca0); __sincosf(a1,&sa1,&ca1);
        __sincosf(b0,&sb0,&cb0); __sincosf(b1,&sb1,&cb1);
        size_t obase = ((size_t)(res*K_ + k))*256 + col;
        __stcs((float2*)&out[obase],       make_float2(ca0+cb0, ca1+cb1));
        __stcs((float2*)&out[obase + 128], make_float2(sa0+sb0, sa1+sb1));
    }
}

// ---------------------------------------------------------------------------
extern "C" void kernel_launch(void* const* d_in, const int* in_sizes, int n_in,
                              void* d_out, int out_size){
    const float* X     = (const float*)d_in[0];
    const void*  eidx  = d_in[1];
    const void*  C     = d_in[2];
    const float* Wvec  = (const float*)d_in[3];
    const float* Wdist = (const float*)d_in[4];
    (void)in_sizes; (void)n_in; (void)out_size;

    wprep_kernel<<<1, 128>>>(Wvec, Wdist);
    edge_kernel<<<BL_, 256>>>(X, eidx, C, (float*)d_out);
}